// round 13
// baseline (speedup 1.0000x reference)
#include <cuda_runtime.h>
#include <cstdint>

// TensorProduct, round 13: unfolded tf32 mma.sync, 12 warps, direct-STG
// epilogue, NO raw buffer: x1(t+1) is LDG'd into held registers before the
// mainloop and converted+STS'd into double-buffered A planes after it.
// One __syncthreads per tile.
//   Y1  = x1s  @ [a0*W1 | a1*W3]               (K=64, N=128)
//   Y2k = x1vk @ [a0/s3*W2 | a1*W4 | a1/s2*W5]  (K=64, N=192; B shared over k)
// 48-row tiles, 12 warps = 3 row-slabs x 4 w-quarters, M16x16w each.

#define NTH   384
#define TILE  48
#define RS    68      // K-row stride in words (bank-staggered, 8B aligned)

#define PLANE (TILE * RS)                 // 3264
#define ABUF  (4 * PLANE)                 // 13056 words per A buffer
#define OFF_A 0
#define OFF_B1 (2 * ABUF)                 // 26112
#define OFF_B2 (OFF_B1 + 128 * RS)        // 34816
#define SMEM_WORDS (OFF_B2 + 192 * RS)    // 47872
#define SMEM_BYTES (SMEM_WORDS * 4)       // 191488

__device__ __forceinline__ uint32_t tf32c(float f) {
    uint32_t u; asm("cvt.rna.tf32.f32 %0, %1;" : "=r"(u) : "f"(f)); return u;
}
// place K so a thread's {k, k+4} pair is one aligned 8B load
__device__ __forceinline__ int swz(int K) {
    return ((K >> 3) << 3) + ((K & 3) << 1) + ((K >> 2) & 1);
}
__device__ __forceinline__ void mma8(float* c, uint32_t a0, uint32_t a1,
                                     uint32_t a2, uint32_t a3,
                                     uint32_t b0, uint32_t b1) {
    asm volatile(
        "mma.sync.aligned.m16n8k8.row.col.f32.tf32.tf32.f32 "
        "{%0,%1,%2,%3}, {%4,%5,%6,%7}, {%8,%9}, {%0,%1,%2,%3};"
        : "+f"(c[0]), "+f"(c[1]), "+f"(c[2]), "+f"(c[3])
        : "r"(a0), "r"(a1), "r"(a2), "r"(a3), "r"(b0), "r"(b1));
}

// convert one held task (row r, u-group g: 4 u's) into the 4 A planes
__device__ __forceinline__ void sts_task(uint32_t* dst, int r, int g,
                                         float4 s4, const float4* v4) {
    const float V[12] = {v4[0].x, v4[0].y, v4[0].z, v4[0].w,
                         v4[1].x, v4[1].y, v4[1].z, v4[1].w,
                         v4[2].x, v4[2].y, v4[2].z, v4[2].w};
    const float S[4] = {s4.x, s4.y, s4.z, s4.w};
    #pragma unroll
    for (int e = 0; e < 4; e++) {
        int ao = r * RS + swz(4 * g + e);
        dst[0 * PLANE + ao] = tf32c(S[e]);
        dst[1 * PLANE + ao] = tf32c(V[3 * e + 0]);
        dst[2 * PLANE + ao] = tf32c(V[3 * e + 1]);
        dst[3 * PLANE + ao] = tf32c(V[3 * e + 2]);
    }
}

__global__ __launch_bounds__(NTH, 1)
void tp_k(const float* __restrict__ x1, const float* __restrict__ x2,
          const float* __restrict__ w1, const float* __restrict__ w2,
          const float* __restrict__ w3, const float* __restrict__ w4,
          const float* __restrict__ w5,
          float* __restrict__ out, int n) {
    extern __shared__ uint32_t sw[];
    const int tid  = threadIdx.x;
    const int lane = tid & 31;
    const int wid  = tid >> 5;
    const int q    = lane & 3;
    const int rsub = lane >> 2;          // 0..7
    const int slab = wid >> 2;           // 0..2  (rows slab*16)
    const int qd   = wid & 3;            // w-quarter: w in [16qd, 16qd+16)

    const float A0   = 0.08838834764831845f;   // sqrt(1/128)
    const float A0S3 = 0.05103103630798288f;   // a0/sqrt(3)
    const float A1   = 0.07216878364870323f;   // sqrt(1/192)
    const float A1R2 = 0.05103103630798288f;   // a1/sqrt(2)

    const int numTiles = (n + TILE - 1) / TILE;

    // per-thread LDG task geometry: tasks tid and tid+NTH
    const int tr0 = tid >> 4,          tg0 = tid & 15;          // task 0
    const int tr1 = (tid + NTH) >> 4,  tg1 = (tid + NTH) & 15;  // task 1

    // ---- stage B with per-thread-aligned column permutation ----
    for (int i = tid; i < 128 * 64; i += NTH) {
        int nn = i >> 6, k = i & 63;
        int qdd = nn >> 5, nl = nn & 31;
        int wp = nl >> 3, rem = nl & 7, qq = rem >> 1, m = rem & 1;
        int w = 16 * qdd + 4 * qq + wp;
        float v = m ? A1 * w3[k * 64 + w] : A0 * w1[k * 64 + w];
        sw[OFF_B1 + nn * RS + swz(k)] = tf32c(v);
    }
    for (int i = tid; i < 192 * 64; i += NTH) {
        int nn = i >> 6, k = i & 63;
        int qdd = nn / 48, nl = nn - 48 * qdd;
        int t = nl >> 3, rem = nl & 7, qq = rem >> 1, j = rem & 1;
        int s = 2 * t + j, wp = s / 3, m = s - 3 * wp;
        int w = 16 * qdd + 4 * qq + wp;
        float v = (m == 0) ? A0S3 * w2[k * 64 + w]
                : (m == 1) ? A1 * w4[k * 64 + w]
                :            A1R2 * w5[k * 64 + w];
        sw[OFF_B2 + nn * RS + swz(k)] = tf32c(v);
    }

    // ---- prologue: LDG + STS first tile into buffer 0 ----
    if (blockIdx.x < numTiles) {
        int row0 = blockIdx.x * TILE;
        float4 s4; float4 v4[3];
        int g0 = row0 + tr0; if (g0 >= n) g0 = 0;
        s4 = *(const float4*)(x1 + (size_t)g0 * 256 + 4 * tg0);
        #pragma unroll
        for (int j = 0; j < 3; j++)
            v4[j] = *(const float4*)(x1 + (size_t)g0 * 256 + 64 + 12 * tg0 + 4 * j);
        sts_task(sw + OFF_A, tr0, tg0, s4, v4);
        int g1 = row0 + tr1; if (g1 >= n) g1 = 0;
        s4 = *(const float4*)(x1 + (size_t)g1 * 256 + 4 * tg1);
        #pragma unroll
        for (int j = 0; j < 3; j++)
            v4[j] = *(const float4*)(x1 + (size_t)g1 * 256 + 64 + 12 * tg1 + 4 * j);
        sts_task(sw + OFF_A, tr1, tg1, s4, v4);
    }
    __syncthreads();

    const int rl0 = slab * 16 + rsub;
    const int wb  = 16 * qd + 4 * q;
    const uint32_t* b1 = sw + OFF_B1 + (32 * qd + rsub) * RS + q * 2;
    const uint32_t* b2 = sw + OFF_B2 + (48 * qd + rsub) * RS + q * 2;

    int p = 0;
    for (int tile = blockIdx.x; tile < numTiles; tile += gridDim.x, p ^= 1) {
        const int row0 = tile * TILE;
        const int ntile = tile + gridDim.x;
        const bool hasNext = (ntile < numTiles);

        // ---- issue next tile's LDGs into held registers ----
        float4 hs0, hs1, hv0[3], hv1[3];
        if (hasNext) {
            int nrow0 = ntile * TILE;
            int g0 = nrow0 + tr0; if (g0 >= n) g0 = 0;
            hs0 = *(const float4*)(x1 + (size_t)g0 * 256 + 4 * tg0);
            #pragma unroll
            for (int j = 0; j < 3; j++)
                hv0[j] = *(const float4*)(x1 + (size_t)g0 * 256 + 64 + 12 * tg0 + 4 * j);
            int g1 = nrow0 + tr1; if (g1 >= n) g1 = 0;
            hs1 = *(const float4*)(x1 + (size_t)g1 * 256 + 4 * tg1);
            #pragma unroll
            for (int j = 0; j < 3; j++)
                hv1[j] = *(const float4*)(x1 + (size_t)g1 * 256 + 64 + 12 * tg1 + 4 * j);
        }

        // x2 for this tile's epilogue rows
        float4 xq0 = make_float4(0.f, 0.f, 0.f, 0.f), xq1 = xq0;
        if (row0 + rl0 < n)     xq0 = *(const float4*)(x2 + (size_t)(row0 + rl0) * 4);
        if (row0 + rl0 + 8 < n) xq1 = *(const float4*)(x2 + (size_t)(row0 + rl0 + 8) * 4);

        // ---- mainloop: K=64 -> 8 k-steps, 22 mma each ----
        float acc1[4][4];
        float acc2[3][6][4];
        #pragma unroll
        for (int t = 0; t < 4; t++)
            #pragma unroll
            for (int c = 0; c < 4; c++) acc1[t][c] = 0.f;
        #pragma unroll
        for (int kv = 0; kv < 3; kv++)
            #pragma unroll
            for (int t = 0; t < 6; t++)
                #pragma unroll
                for (int c = 0; c < 4; c++) acc2[kv][t][c] = 0.f;

        const uint32_t* aS = sw + OFF_A + p * ABUF + rl0 * RS + q * 2;
        #pragma unroll
        for (int ks = 0; ks < 8; ks++) {
            uint2 sl = *(const uint2*)(aS + ks * 8);
            uint2 sh = *(const uint2*)(aS + 8 * RS + ks * 8);
            uint2 vl[3], vh[3];
            #pragma unroll
            for (int kv = 0; kv < 3; kv++) {
                vl[kv] = *(const uint2*)(aS + (kv + 1) * PLANE + ks * 8);
                vh[kv] = *(const uint2*)(aS + (kv + 1) * PLANE + 8 * RS + ks * 8);
            }
            #pragma unroll
            for (int t = 0; t < 4; t++) {
                uint2 b = *(const uint2*)(b1 + t * 8 * RS + ks * 8);
                mma8(acc1[t], sl.x, sh.x, sl.y, sh.y, b.x, b.y);
            }
            #pragma unroll
            for (int t = 0; t < 6; t++) {
                uint2 b = *(const uint2*)(b2 + t * 8 * RS + ks * 8);
                mma8(acc2[0][t], vl[0].x, vh[0].x, vl[0].y, vh[0].y, b.x, b.y);
                mma8(acc2[1][t], vl[1].x, vh[1].x, vl[1].y, vh[1].y, b.x, b.y);
                mma8(acc2[2][t], vl[2].x, vh[2].x, vl[2].y, vh[2].y, b.x, b.y);
            }
        }

        // ---- epilogue: combine with x2 in-register, STG.128 direct ----
        #pragma unroll
        for (int p2 = 0; p2 < 2; p2++) {
            int grow = row0 + rl0 + 8 * p2;
            if (grow >= n) continue;
            float xs  = p2 ? xq1.x : xq0.x;
            float xv0 = p2 ? xq1.y : xq0.y;
            float xv1 = p2 ? xq1.z : xq0.z;
            float xv2 = p2 ? xq1.w : xq0.w;
            float os4[4], ov[12];
            #pragma unroll
            for (int wp = 0; wp < 4; wp++) {
                float y1 = acc1[wp][2 * p2 + 0];
                float y3 = acc1[wp][2 * p2 + 1];
                int s0 = 3 * wp,     t0 = s0 >> 1, j0 = s0 & 1;
                int s1 = 3 * wp + 1, t1 = s1 >> 1, j1 = s1 & 1;
                int s2 = 3 * wp + 2, t2 = s2 >> 1, j2 = s2 & 1;
                float y2a = acc2[0][t0][2 * p2 + j0];
                float y2b = acc2[1][t0][2 * p2 + j0];
                float y2c = acc2[2][t0][2 * p2 + j0];
                float y4a = acc2[0][t1][2 * p2 + j1];
                float y4b = acc2[1][t1][2 * p2 + j1];
                float y4c = acc2[2][t1][2 * p2 + j1];
                float y5a = acc2[0][t2][2 * p2 + j2];
                float y5b = acc2[1][t2][2 * p2 + j2];
                float y5c = acc2[2][t2][2 * p2 + j2];

                os4[wp] = xs * y1 + xv0 * y2a + xv1 * y2b + xv2 * y2c;
                ov[3 * wp + 0] = xv0 * y3 + xs * y4a + (y5b * xv2 - y5c * xv1);
                ov[3 * wp + 1] = xv1 * y3 + xs * y4b + (y5c * xv0 - y5a * xv2);
                ov[3 * wp + 2] = xv2 * y3 + xs * y4c + (y5a * xv1 - y5b * xv0);
            }
            float* orow = out + (size_t)grow * 256;
            *(float4*)(orow + wb) = make_float4(os4[0], os4[1], os4[2], os4[3]);
            *(float4*)(orow + 64 + 3 * wb + 0) =
                make_float4(ov[0], ov[1], ov[2], ov[3]);
            *(float4*)(orow + 64 + 3 * wb + 4) =
                make_float4(ov[4], ov[5], ov[6], ov[7]);
            *(float4*)(orow + 64 + 3 * wb + 8) =
                make_float4(ov[8], ov[9], ov[10], ov[11]);
        }

        // ---- convert held regs -> other A buffer (no conflict with buf p) ----
        if (hasNext) {
            uint32_t* dst = sw + OFF_A + (p ^ 1) * ABUF;
            sts_task(dst, tr0, tg0, hs0, hv0);
            sts_task(dst, tr1, tg1, hs1, hv1);
        }
        __syncthreads();   // STS visible to all; everyone done with buf p
    }
}

extern "C" void kernel_launch(void* const* d_in, const int* in_sizes, int n_in,
                              void* d_out, int out_size) {
    const float* x1 = (const float*)d_in[0];
    const float* x2 = (const float*)d_in[1];
    const float* w1 = (const float*)d_in[2];   // w_ss_s
    const float* w2 = (const float*)d_in[3];   // w_vv_s
    const float* w3 = (const float*)d_in[4];   // w_sv_v
    const float* w4 = (const float*)d_in[5];   // w_vs_v
    const float* w5 = (const float*)d_in[6];   // w_vv_v
    float* out = (float*)d_out;

    int n = in_sizes[0] / 256;
    cudaFuncSetAttribute(tp_k, cudaFuncAttributeMaxDynamicSharedMemorySize,
                         SMEM_BYTES);
    int numTiles = (n + TILE - 1) / TILE;
    int grid = numTiles < 148 ? numTiles : 148;
    tp_k<<<grid, NTH, SMEM_BYTES>>>(x1, x2, w1, w2, w3, w4, w5, out, n);
}

// round 14
// speedup vs baseline: 1.2127x; 1.2127x over previous
#include <cuda_runtime.h>
#include <cstdint>

// TensorProduct, round 14: identical to round 12 except RS=68 -> 72, which
// makes every mainloop fragment LDS.64 bank-conflict-free per half-warp phase
// (base 8*rsub mod 32 = {0,8,16,24} per phase, +2q+{0,1} tiles all 32 banks).
//   Y1  = x1s  @ [a0*W1 | a1*W3]               (K=64, N=128)
//   Y2k = x1vk @ [a0/s3*W2 | a1*W4 | a1/s2*W5]  (K=64, N=192; B shared over k)
// 48-row tiles, 12 warps = 3 row-slabs x 4 w-quarters, M16x16w each.

#define NTH   384
#define TILE  48
#define RS    72      // K-row stride in words: 8 mod 32 -> phase-conflict-free

#define OFF_RAW  0
#define RAW_WORDS (TILE * 256)                  // 12288
#define PLANE    (TILE * RS)                    // 3456
#define OFF_AS   RAW_WORDS
#define OFF_B1   (OFF_AS + 4 * PLANE)           // 26112
#define OFF_B2   (OFF_B1 + 128 * RS)            // 35328
#define SMEM_WORDS (OFF_B2 + 192 * RS)          // 49152
#define SMEM_BYTES (SMEM_WORDS * 4)             // 196608

__device__ __forceinline__ uint32_t tf32c(float f) {
    uint32_t u; asm("cvt.rna.tf32.f32 %0, %1;" : "=r"(u) : "f"(f)); return u;
}
// place K so a thread's {k, k+4} pair is one aligned 8B load
__device__ __forceinline__ int swz(int K) {
    return ((K >> 3) << 3) + ((K & 3) << 1) + ((K >> 2) & 1);
}
__device__ __forceinline__ uint32_t smem_u32(const void* p) {
    uint32_t a;
    asm("{ .reg .u64 t; cvta.to.shared.u64 t, %1; cvt.u32.u64 %0, t; }"
        : "=r"(a) : "l"(p));
    return a;
}
__device__ __forceinline__ void mma8(float* c, uint32_t a0, uint32_t a1,
                                     uint32_t a2, uint32_t a3,
                                     uint32_t b0, uint32_t b1) {
    asm volatile(
        "mma.sync.aligned.m16n8k8.row.col.f32.tf32.tf32.f32 "
        "{%0,%1,%2,%3}, {%4,%5,%6,%7}, {%8,%9}, {%0,%1,%2,%3};"
        : "+f"(c[0]), "+f"(c[1]), "+f"(c[2]), "+f"(c[3])
        : "r"(a0), "r"(a1), "r"(a2), "r"(a3), "r"(b0), "r"(b1));
}
__device__ __forceinline__ void cpa16(uint32_t dst, const void* src) {
    asm volatile("cp.async.cg.shared.global [%0], [%1], 16;"
                 :: "r"(dst), "l"(src));
}

__global__ __launch_bounds__(NTH, 1)
void tp_k(const float* __restrict__ x1, const float* __restrict__ x2,
          const float* __restrict__ w1, const float* __restrict__ w2,
          const float* __restrict__ w3, const float* __restrict__ w4,
          const float* __restrict__ w5,
          float* __restrict__ out, int n) {
    extern __shared__ uint32_t sw[];
    const int tid  = threadIdx.x;
    const int lane = tid & 31;
    const int wid  = tid >> 5;
    const int q    = lane & 3;
    const int rsub = lane >> 2;          // 0..7
    const int slab = wid >> 2;           // 0..2  (rows slab*16)
    const int qd   = wid & 3;            // w-quarter: w in [16qd, 16qd+16)

    const float A0   = 0.08838834764831845f;   // sqrt(1/128)
    const float A0S3 = 0.05103103630798288f;   // a0/sqrt(3)
    const float A1   = 0.07216878364870323f;   // sqrt(1/192)
    const float A1R2 = 0.05103103630798288f;   // a1/sqrt(2)

    const int numTiles = (n + TILE - 1) / TILE;
    const uint32_t sbRaw = smem_u32(sw + OFF_RAW);

    // ---- prologue: cp.async first tile into raw ----
    {
        int row0 = blockIdx.x * TILE;
        #pragma unroll
        for (int it = 0; it < 8; it++) {
            int idx = tid + it * NTH;               // 3072 16B chunks
            int r = idx >> 6, c = (idx & 63) << 2;
            int grow = row0 + r; if (grow >= n) grow = 0;
            cpa16(sbRaw + (idx << 4), x1 + (size_t)grow * 256 + c);
        }
    }
    asm volatile("cp.async.commit_group;" ::: "memory");

    // ---- stage B with per-thread-aligned column permutation ----
    // B1: n = 32*qd' + 8*w' + 2*q' + m   (m=0 -> a0*W1 (y1), m=1 -> a1*W3 (y3))
    for (int i = tid; i < 128 * 64; i += NTH) {
        int nn = i >> 6, k = i & 63;
        int qdd = nn >> 5, nl = nn & 31;
        int wp = nl >> 3, rem = nl & 7, qq = rem >> 1, m = rem & 1;
        int w = 16 * qdd + 4 * qq + wp;
        float v = m ? A1 * w3[k * 64 + w] : A0 * w1[k * 64 + w];
        sw[OFF_B1 + nn * RS + swz(k)] = tf32c(v);
    }
    // B2: n = 48*qd' + 8*t + 2*q' + j ; s=2t+j; w'=s/3; m=s%3
    for (int i = tid; i < 192 * 64; i += NTH) {
        int nn = i >> 6, k = i & 63;
        int qdd = nn / 48, nl = nn - 48 * qdd;
        int t = nl >> 3, rem = nl & 7, qq = rem >> 1, j = rem & 1;
        int s = 2 * t + j, wp = s / 3, m = s - 3 * wp;
        int w = 16 * qdd + 4 * qq + wp;
        float v = (m == 0) ? A0S3 * w2[k * 64 + w]
                : (m == 1) ? A1 * w4[k * 64 + w]
                :            A1R2 * w5[k * 64 + w];
        sw[OFF_B2 + nn * RS + swz(k)] = tf32c(v);
    }

    const int rl0 = slab * 16 + rsub;
    const int wb  = 16 * qd + 4 * q;
    const uint32_t* aS = sw + OFF_AS + rl0 * RS + q * 2;
    const uint32_t* b1 = sw + OFF_B1 + (32 * qd + rsub) * RS + q * 2;
    const uint32_t* b2 = sw + OFF_B2 + (48 * qd + rsub) * RS + q * 2;
    const float* rawf = (const float*)(sw + OFF_RAW);

    for (int tile = blockIdx.x; tile < numTiles; tile += gridDim.x) {
        const int row0 = tile * TILE;

        // ---- wait raw, repack A into tf32 planes; prefetch x2 ----
        asm volatile("cp.async.wait_group 0;" ::: "memory");
        __syncthreads();

        float4 xq0 = make_float4(0.f, 0.f, 0.f, 0.f), xq1 = xq0;
        if (row0 + rl0 < n)     xq0 = *(const float4*)(x2 + (size_t)(row0 + rl0) * 4);
        if (row0 + rl0 + 8 < n) xq1 = *(const float4*)(x2 + (size_t)(row0 + rl0 + 8) * 4);

        #pragma unroll
        for (int it = 0; it < 8; it++) {
            int cell = tid + it * NTH;               // 3072 = 48 rows x 64 u
            int r = cell >> 6, u = cell & 63;
            float s  = rawf[r * 256 + u];
            float v0 = rawf[r * 256 + 64 + 3 * u];
            float v1 = rawf[r * 256 + 64 + 3 * u + 1];
            float v2 = rawf[r * 256 + 64 + 3 * u + 2];
            int ao = r * RS + swz(u);
            sw[OFF_AS + 0 * PLANE + ao] = tf32c(s);
            sw[OFF_AS + 1 * PLANE + ao] = tf32c(v0);
            sw[OFF_AS + 2 * PLANE + ao] = tf32c(v1);
            sw[OFF_AS + 3 * PLANE + ao] = tf32c(v2);
        }
        __syncthreads();   // planes ready; raw free

        // ---- issue next tile's cp.async (hidden under mainloop) ----
        int ntile = tile + gridDim.x;
        if (ntile < numTiles) {
            int nrow0 = ntile * TILE;
            #pragma unroll
            for (int it = 0; it < 8; it++) {
                int idx = tid + it * NTH;
                int r = idx >> 6, c = (idx & 63) << 2;
                int grow = nrow0 + r; if (grow >= n) grow = 0;
                cpa16(sbRaw + (idx << 4), x1 + (size_t)grow * 256 + c);
            }
        }
        asm volatile("cp.async.commit_group;" ::: "memory");

        // ---- mainloop: K=64 -> 8 k-steps, 22 mma each ----
        float acc1[4][4];
        float acc2[3][6][4];
        #pragma unroll
        for (int t = 0; t < 4; t++)
            #pragma unroll
            for (int c = 0; c < 4; c++) acc1[t][c] = 0.f;
        #pragma unroll
        for (int kv = 0; kv < 3; kv++)
            #pragma unroll
            for (int t = 0; t < 6; t++)
                #pragma unroll
                for (int c = 0; c < 4; c++) acc2[kv][t][c] = 0.f;

        #pragma unroll
        for (int ks = 0; ks < 8; ks++) {
            uint2 sl = *(const uint2*)(aS + ks * 8);
            uint2 sh = *(const uint2*)(aS + 8 * RS + ks * 8);
            uint2 vl[3], vh[3];
            #pragma unroll
            for (int kv = 0; kv < 3; kv++) {
                vl[kv] = *(const uint2*)(aS + (kv + 1) * PLANE + ks * 8);
                vh[kv] = *(const uint2*)(aS + (kv + 1) * PLANE + 8 * RS + ks * 8);
            }
            #pragma unroll
            for (int t = 0; t < 4; t++) {
                uint2 b = *(const uint2*)(b1 + t * 8 * RS + ks * 8);
                mma8(acc1[t], sl.x, sh.x, sl.y, sh.y, b.x, b.y);
            }
            #pragma unroll
            for (int t = 0; t < 6; t++) {
                uint2 b = *(const uint2*)(b2 + t * 8 * RS + ks * 8);
                mma8(acc2[0][t], vl[0].x, vh[0].x, vl[0].y, vh[0].y, b.x, b.y);
                mma8(acc2[1][t], vl[1].x, vh[1].x, vl[1].y, vh[1].y, b.x, b.y);
                mma8(acc2[2][t], vl[2].x, vh[2].x, vl[2].y, vh[2].y, b.x, b.y);
            }
        }

        // ---- epilogue: combine with x2 in-register, STG.128 direct ----
        #pragma unroll
        for (int p2 = 0; p2 < 2; p2++) {
            int grow = row0 + rl0 + 8 * p2;
            if (grow >= n) continue;
            float xs  = p2 ? xq1.x : xq0.x;
            float xv0 = p2 ? xq1.y : xq0.y;
            float xv1 = p2 ? xq1.z : xq0.z;
            float xv2 = p2 ? xq1.w : xq0.w;
            float os4[4], ov[12];
            #pragma unroll
            for (int wp = 0; wp < 4; wp++) {
                float y1 = acc1[wp][2 * p2 + 0];
                float y3 = acc1[wp][2 * p2 + 1];
                int s0 = 3 * wp,     t0 = s0 >> 1, j0 = s0 & 1;
                int s1 = 3 * wp + 1, t1 = s1 >> 1, j1 = s1 & 1;
                int s2 = 3 * wp + 2, t2 = s2 >> 1, j2 = s2 & 1;
                float y2a = acc2[0][t0][2 * p2 + j0];
                float y2b = acc2[1][t0][2 * p2 + j0];
                float y2c = acc2[2][t0][2 * p2 + j0];
                float y4a = acc2[0][t1][2 * p2 + j1];
                float y4b = acc2[1][t1][2 * p2 + j1];
                float y4c = acc2[2][t1][2 * p2 + j1];
                float y5a = acc2[0][t2][2 * p2 + j2];
                float y5b = acc2[1][t2][2 * p2 + j2];
                float y5c = acc2[2][t2][2 * p2 + j2];

                os4[wp] = xs * y1 + xv0 * y2a + xv1 * y2b + xv2 * y2c;
                ov[3 * wp + 0] = xv0 * y3 + xs * y4a + (y5b * xv2 - y5c * xv1);
                ov[3 * wp + 1] = xv1 * y3 + xs * y4b + (y5c * xv0 - y5a * xv2);
                ov[3 * wp + 2] = xv2 * y3 + xs * y4c + (y5a * xv1 - y5b * xv0);
            }
            float* orow = out + (size_t)grow * 256;
            *(float4*)(orow + wb) = make_float4(os4[0], os4[1], os4[2], os4[3]);
            *(float4*)(orow + 64 + 3 * wb + 0) =
                make_float4(ov[0], ov[1], ov[2], ov[3]);
            *(float4*)(orow + 64 + 3 * wb + 4) =
                make_float4(ov[4], ov[5], ov[6], ov[7]);
            *(float4*)(orow + 64 + 3 * wb + 8) =
                make_float4(ov[8], ov[9], ov[10], ov[11]);
        }
    }
}

extern "C" void kernel_launch(void* const* d_in, const int* in_sizes, int n_in,
                              void* d_out, int out_size) {
    const float* x1 = (const float*)d_in[0];
    const float* x2 = (const float*)d_in[1];
    const float* w1 = (const float*)d_in[2];   // w_ss_s
    const float* w2 = (const float*)d_in[3];   // w_vv_s
    const float* w3 = (const float*)d_in[4];   // w_sv_v
    const float* w4 = (const float*)d_in[5];   // w_vs_v
    const float* w5 = (const float*)d_in[6];   // w_vv_v
    float* out = (float*)d_out;

    int n = in_sizes[0] / 256;
    cudaFuncSetAttribute(tp_k, cudaFuncAttributeMaxDynamicSharedMemorySize,
                         SMEM_BYTES);
    int numTiles = (n + TILE - 1) / TILE;
    int grid = numTiles < 148 ? numTiles : 148;
    tp_k<<<grid, NTH, SMEM_BYTES>>>(x1, x2, w1, w2, w3, w4, w5, out, n);
}